// round 1
// baseline (speedup 1.0000x reference)
#include <cuda_runtime.h>

#define NB   8
#define HW   2304
#define DD   1024
#define NROW (NB * HW)

// Scratch (allocation-free rule: __device__ globals)
__device__ float g_fa[(size_t)NROW * DD];   // normalized A, scaled by 1/TEMP = 10
__device__ float g_fb[(size_t)NROW * DD];   // normalized B
__device__ float g_pos[(size_t)HW * DD];    // fourier positional embedding (batch-invariant)

// ---------------------------------------------------------------------------
// Row L2-normalization. grid = (NROW, 2); block = 256 (1024 floats = 256 float4)
// ---------------------------------------------------------------------------
__global__ __launch_bounds__(256) void normalize_kernel(
    const float* __restrict__ A, const float* __restrict__ Bm)
{
    const int row   = blockIdx.x;
    const int which = blockIdx.y;            // 0 -> A, 1 -> B
    const float* src = which ? Bm : A;
    float*       dst = which ? g_fb : g_fa;
    const size_t base = (size_t)row * DD;

    float4 v = ((const float4*)(src + base))[threadIdx.x];
    float ss = v.x * v.x + v.y * v.y + v.z * v.z + v.w * v.w;
    #pragma unroll
    for (int o = 16; o; o >>= 1) ss += __shfl_xor_sync(0xffffffffu, ss, o);

    __shared__ float ws[8];
    if ((threadIdx.x & 31) == 0) ws[threadIdx.x >> 5] = ss;
    __syncthreads();
    float tot = 0.f;
    #pragma unroll
    for (int i = 0; i < 8; i++) tot += ws[i];

    const float inv = rsqrtf(tot) * (which ? 1.0f : 10.0f);  // fold 1/TEMP into fa
    v.x *= inv; v.y *= inv; v.z *= inv; v.w *= inv;
    ((float4*)(dst + base))[threadIdx.x] = v;
}

// ---------------------------------------------------------------------------
// Fourier positional embedding over the 48x48 grid of image B.
// grid = HW blocks, 512 threads (one per omega row).
// pos[p, k]      = sin(scale * (gx*om[k].x + gy*om[k].y))
// pos[p, 512+k]  = cos(...)
// ---------------------------------------------------------------------------
__global__ __launch_bounds__(512) void posemb_kernel(
    const float* __restrict__ omega, const float* __restrict__ scale)
{
    const int p = blockIdx.x;
    const int k = threadIdx.x;                 // 0..511
    const int i = p / 48, j = p % 48;
    const float gy = -1.0f + 2.0f * (float)i / 47.0f;
    const float gx = -1.0f + 2.0f * (float)j / 47.0f;
    const float s  = *scale;

    const float2 om = ((const float2*)omega)[k];
    const float e = s * (gx * om.x + gy * om.y);
    float sn, cs;
    sincosf(e, &sn, &cs);
    g_pos[(size_t)p * DD + k]        = sn;
    g_pos[(size_t)p * DD + 512 + k]  = cs;
}

// ---------------------------------------------------------------------------
// Tiled SGEMM: C[M,N] = A[M,K] * op(B), batched over blockIdx.z.
//   BT = true : B is [N,K] row-major (K contiguous)   -> C = A * B^T   (GEMM1)
//   BT = false: B is [K,N] row-major (N contiguous)   -> C = A * B     (GEMM2)
// Block tile 128x128, K-tile 8, 256 threads, 8x8 per-thread microtile.
// M, N, K assumed multiples of 128/128/8 (true here: 2304, 1024).
// ---------------------------------------------------------------------------
template <bool BT>
__global__ __launch_bounds__(256) void sgemm_kernel(
    const float* __restrict__ A, const float* __restrict__ B, float* __restrict__ C,
    int N, int K,
    size_t strideA, size_t strideB, size_t strideC)
{
    __shared__ float As[8][128];   // stored transposed: As[k][m]
    __shared__ float Bs[8][128];   // Bs[k][n]

    const int tid = threadIdx.x;
    const int bm  = blockIdx.y * 128;
    const int bn  = blockIdx.x * 128;
    const int tx  = tid & 15;      // 0..15 -> n
    const int ty  = tid >> 4;      // 0..15 -> m

    A += (size_t)blockIdx.z * strideA;
    B += (size_t)blockIdx.z * strideB;
    C += (size_t)blockIdx.z * strideC;

    // A-tile load pattern: 128 rows x 8 k = 256 float4, one per thread
    const int arow = tid >> 1;             // 0..127
    const int acol = (tid & 1) * 4;        // 0 or 4
    const float* Aptr = A + (size_t)(bm + arow) * K + acol;

    const float* Bptr;
    int b_nrow = 0, b_ncol = 0;
    if (BT) {
        Bptr = B + (size_t)(bn + arow) * K + acol;       // [N,K]
    } else {
        b_nrow = tid >> 5;                               // k within tile: 0..7
        b_ncol = (tid & 31) * 4;                         // n within tile
        Bptr = B + (size_t)b_nrow * N + bn + b_ncol;     // [K,N]
    }

    float acc[8][8];
    #pragma unroll
    for (int i = 0; i < 8; i++)
        #pragma unroll
        for (int j = 0; j < 8; j++) acc[i][j] = 0.f;

    for (int kt = 0; kt < K; kt += 8) {
        float4 a = *(const float4*)(Aptr + kt);
        As[acol + 0][arow] = a.x;
        As[acol + 1][arow] = a.y;
        As[acol + 2][arow] = a.z;
        As[acol + 3][arow] = a.w;

        if (BT) {
            float4 b = *(const float4*)(Bptr + kt);
            Bs[acol + 0][arow] = b.x;
            Bs[acol + 1][arow] = b.y;
            Bs[acol + 2][arow] = b.z;
            Bs[acol + 3][arow] = b.w;
        } else {
            float4 b = *(const float4*)(Bptr + (size_t)kt * N);
            *(float4*)&Bs[b_nrow][b_ncol] = b;
        }
        __syncthreads();

        #pragma unroll
        for (int kk = 0; kk < 8; kk++) {
            float ar[8], br[8];
            *(float4*)(ar)     = *(const float4*)&As[kk][ty * 8];
            *(float4*)(ar + 4) = *(const float4*)&As[kk][ty * 8 + 4];
            *(float4*)(br)     = *(const float4*)&Bs[kk][tx * 8];
            *(float4*)(br + 4) = *(const float4*)&Bs[kk][tx * 8 + 4];
            #pragma unroll
            for (int i = 0; i < 8; i++)
                #pragma unroll
                for (int j = 0; j < 8; j++)
                    acc[i][j] = fmaf(ar[i], br[j], acc[i][j]);
        }
        __syncthreads();
    }

    #pragma unroll
    for (int i = 0; i < 8; i++) {
        float* cp = C + (size_t)(bm + ty * 8 + i) * N + bn + tx * 8;
        ((float4*)cp)[0] = make_float4(acc[i][0], acc[i][1], acc[i][2], acc[i][3]);
        ((float4*)cp)[1] = make_float4(acc[i][4], acc[i][5], acc[i][6], acc[i][7]);
    }
}

// ---------------------------------------------------------------------------
// Row softmax over HW=2304 columns. One block per row, 256 threads.
// ---------------------------------------------------------------------------
__global__ __launch_bounds__(256) void softmax_kernel(
    const float* __restrict__ logits, float* __restrict__ attn)
{
    const size_t row = blockIdx.x;
    const float4* src = (const float4*)(logits + row * HW);
    float4*       dst = (float4*)(attn   + row * HW);
    __shared__ float4 buf[HW / 4];     // 576 float4 = 9216 B
    __shared__ float  red[8];
    const int tid = threadIdx.x;

    float m = -1e30f;
    for (int i = tid; i < HW / 4; i += 256) {
        float4 v = src[i];
        buf[i] = v;
        m = fmaxf(m, fmaxf(fmaxf(v.x, v.y), fmaxf(v.z, v.w)));
    }
    #pragma unroll
    for (int o = 16; o; o >>= 1) m = fmaxf(m, __shfl_xor_sync(0xffffffffu, m, o));
    if ((tid & 31) == 0) red[tid >> 5] = m;
    __syncthreads();
    float M = red[0];
    #pragma unroll
    for (int i = 1; i < 8; i++) M = fmaxf(M, red[i]);
    __syncthreads();   // protect red before reuse

    float s = 0.f;
    for (int i = tid; i < HW / 4; i += 256) {
        float4 v = buf[i];
        v.x = __expf(v.x - M); v.y = __expf(v.y - M);
        v.z = __expf(v.z - M); v.w = __expf(v.w - M);
        buf[i] = v;
        s += v.x + v.y + v.z + v.w;
    }
    #pragma unroll
    for (int o = 16; o; o >>= 1) s += __shfl_xor_sync(0xffffffffu, s, o);
    if ((tid & 31) == 0) red[tid >> 5] = s;
    __syncthreads();
    float S = 0.f;
    #pragma unroll
    for (int i = 0; i < 8; i++) S += red[i];
    const float inv = 1.0f / S;

    for (int i = tid; i < HW / 4; i += 256) {
        float4 v = buf[i];
        v.x *= inv; v.y *= inv; v.z *= inv; v.w *= inv;
        dst[i] = v;
    }
}

// ---------------------------------------------------------------------------
extern "C" void kernel_launch(void* const* d_in, const int* in_sizes, int n_in,
                              void* d_out, int out_size)
{
    const float* fA    = (const float*)d_in[0];
    const float* fB    = (const float*)d_in[1];
    const float* omega = (const float*)d_in[2];
    const float* scale = (const float*)d_in[3];

    float* out    = (float*)d_out;
    float* logits = out;                                   // [NB, HW, HW]
    float* attn   = out + (size_t)NB * HW * HW;            // [NB, HW, HW]
    float* match  = attn + (size_t)NB * HW * HW;           // [NB, HW, DD]

    float *fa_p, *fb_p, *pos_p;
    cudaGetSymbolAddress((void**)&fa_p,  g_fa);
    cudaGetSymbolAddress((void**)&fb_p,  g_fb);
    cudaGetSymbolAddress((void**)&pos_p, g_pos);

    // 1) normalize both feature maps (fa scaled by 1/TEMP)
    normalize_kernel<<<dim3(NROW, 2), 256>>>(fA, fB);

    // 2) positional embedding (batch-invariant)
    posemb_kernel<<<HW, 512>>>(omega, scale);

    // 3) GEMM1: logits[b] = fa_n[b] @ fb_n[b]^T     (B is [N,K] -> BT=true)
    {
        dim3 grid(HW / 128, HW / 128, NB);
        sgemm_kernel<true><<<grid, 256>>>(
            fa_p, fb_p, logits, HW, DD,
            (size_t)HW * DD, (size_t)HW * DD, (size_t)HW * HW);
    }

    // 4) row softmax
    softmax_kernel<<<NROW, 256>>>(logits, attn);

    // 5) GEMM2: match[b] = attn[b] @ pos_emb        (B is [K,N] -> BT=false)
    {
        dim3 grid(DD / 128, HW / 128, NB);
        sgemm_kernel<false><<<grid, 256>>>(
            attn, pos_p, match, DD, HW,
            (size_t)HW * HW, (size_t)0, (size_t)HW * DD);
    }
}

// round 3
// speedup vs baseline: 3.0330x; 3.0330x over previous
#include <cuda_runtime.h>
#include <cstdint>

#define NB   8
#define HW   2304
#define DD   1024
#define NROW (NB * HW)

// ------------------------------ scratch ------------------------------------
__device__ float g_fa[(size_t)NROW * DD];   // normalized A (tf32-rounded, x10 = 1/TEMP)
__device__ float g_fb[(size_t)NROW * DD];   // normalized B (tf32-rounded)
__device__ float g_posT[(size_t)DD * HW];   // pos emb transposed [D][HW], tf32-rounded

// ------------------------------ helpers ------------------------------------
__device__ __forceinline__ uint32_t smem_u32(const void* p) {
    uint32_t a;
    asm("{ .reg .u64 t; cvta.to.shared.u64 t, %1; cvt.u32.u64 %0, t; }" : "=r"(a) : "l"(p));
    return a;
}
__device__ __forceinline__ float tf32r(float x) {
    uint32_t u;
    asm("cvt.rna.tf32.f32 %0, %1;" : "=r"(u) : "f"(x));
    return __uint_as_float(u);
}
__device__ __forceinline__ void cpa16(uint32_t dst, const void* src) {
    asm volatile("cp.async.cg.shared.global [%0], [%1], 16;" :: "r"(dst), "l"(src));
}
__device__ __forceinline__ void cpa_commit() {
    asm volatile("cp.async.commit_group;" ::: "memory");
}
__device__ __forceinline__ void cpa_wait1() {
    asm volatile("cp.async.wait_group 1;" ::: "memory");
}
// D += A * B^T  via m16n8k8 tf32 (row.col)
__device__ __forceinline__ void mma_tf32(float* c, const uint32_t* a, const uint32_t* b) {
    asm volatile(
        "mma.sync.aligned.m16n8k8.row.col.f32.tf32.tf32.f32 "
        "{%0,%1,%2,%3}, {%4,%5,%6,%7}, {%8,%9}, {%0,%1,%2,%3};"
        : "+f"(c[0]), "+f"(c[1]), "+f"(c[2]), "+f"(c[3])
        : "r"(a[0]), "r"(a[1]), "r"(a[2]), "r"(a[3]), "r"(b[0]), "r"(b[1]));
}

// ---------------------------------------------------------------------------
// Row L2-normalization + tf32 rounding. grid=(NROW,2), block=256.
// ---------------------------------------------------------------------------
__global__ __launch_bounds__(256) void normalize_kernel(
    const float* __restrict__ A, const float* __restrict__ Bm)
{
    const int row   = blockIdx.x;
    const int which = blockIdx.y;
    const float* src = which ? Bm : A;
    float*       dst = which ? g_fb : g_fa;
    const size_t base = (size_t)row * DD;

    float4 v = ((const float4*)(src + base))[threadIdx.x];
    float ss = v.x * v.x + v.y * v.y + v.z * v.z + v.w * v.w;
    #pragma unroll
    for (int o = 16; o; o >>= 1) ss += __shfl_xor_sync(0xffffffffu, ss, o);

    __shared__ float ws[8];
    if ((threadIdx.x & 31) == 0) ws[threadIdx.x >> 5] = ss;
    __syncthreads();
    float tot = 0.f;
    #pragma unroll
    for (int i = 0; i < 8; i++) tot += ws[i];

    const float inv = rsqrtf(tot) * (which ? 1.0f : 10.0f);
    v.x = tf32r(v.x * inv); v.y = tf32r(v.y * inv);
    v.z = tf32r(v.z * inv); v.w = tf32r(v.w * inv);
    ((float4*)(dst + base))[threadIdx.x] = v;
}

// ---------------------------------------------------------------------------
// Fourier pos-emb written TRANSPOSED: g_posT[d][p]. grid=512 (omega rows).
// ---------------------------------------------------------------------------
__global__ __launch_bounds__(256) void posemb_kernel(
    const float* __restrict__ omega, const float* __restrict__ scale)
{
    const int k = blockIdx.x;                  // 0..511
    const float2 om = ((const float2*)omega)[k];
    const float s  = *scale;
    float* rsin = g_posT + (size_t)k * HW;
    float* rcos = g_posT + (size_t)(512 + k) * HW;

    for (int p = threadIdx.x; p < HW; p += 256) {
        const int i = p / 48, j = p % 48;
        const float gy = -1.0f + 2.0f * (float)i / 47.0f;
        const float gx = -1.0f + 2.0f * (float)j / 47.0f;
        float sn, cs;
        sincosf(s * (gx * om.x + gy * om.y), &sn, &cs);
        rsin[p] = tf32r(sn);
        rcos[p] = tf32r(cs);
    }
}

// ---------------------------------------------------------------------------
// tf32 mma.sync GEMM: C[M,N] = A[M,K] * B[N,K]^T, batched on blockIdx.z.
// Tile 128x128, BK=16, 3-stage cp.async pipeline, 8 warps (warp tile 64x32).
// A, B row-major with K contiguous; all dims multiples of tile sizes.
// ---------------------------------------------------------------------------
#define BM 128
#define BN 128
#define BK 16
#define PADK 20                       // BK + 4 floats padding (bank-conflict-free)
#define STAGE_FLOATS ((BM + BN) * PADK)     // 5120 floats = 20480 B
#define NSTG 3

extern __shared__ float smf[];

__global__ __launch_bounds__(256, 2)
void gemm_tf32_kernel(const float* __restrict__ A, const float* __restrict__ B,
                      float* __restrict__ C,
                      int K, int lda, int ldb, int ldc,
                      size_t sA, size_t sB, size_t sC)
{
    const uint32_t sbase = smem_u32(smf);
    const int tid  = threadIdx.x;
    const int wid  = tid >> 5;
    const int lane = tid & 31;
    const int bm = blockIdx.y * BM;
    const int bn = blockIdx.x * BN;

    A += (size_t)blockIdx.z * sA;
    B += (size_t)blockIdx.z * sB;
    C += (size_t)blockIdx.z * sC;

    // ---- loader addressing: thread owns rows r, r+64 at float4-col kc ----
    const int r  = tid >> 2;           // 0..63
    const int kc = tid & 3;            // 0..3 -> floats kc*4
    const float* pa0 = A + (size_t)(bm + r) * lda + kc * 4;
    const float* pa1 = pa0 + (size_t)64 * lda;
    const float* pb0 = B + (size_t)(bn + r) * ldb + kc * 4;
    const float* pb1 = pb0 + (size_t)64 * ldb;
    const uint32_t da0 = sbase + (uint32_t)(r * PADK + kc * 4) * 4;
    const uint32_t da1 = da0 + 64 * PADK * 4;
    const uint32_t db0 = da0 + BM * PADK * 4;
    const uint32_t db1 = db0 + 64 * PADK * 4;

    const int nkt = K / BK;

    #define ISSUE(kt, s) do {                                        \
        const uint32_t o = (uint32_t)(s) * (STAGE_FLOATS * 4);       \
        const int off = (kt) * BK;                                   \
        cpa16(da0 + o, pa0 + off);                                   \
        cpa16(da1 + o, pa1 + off);                                   \
        cpa16(db0 + o, pb0 + off);                                   \
        cpa16(db1 + o, pb1 + off);                                   \
        cpa_commit();                                                \
    } while (0)

    ISSUE(0, 0);
    ISSUE(1, 1);

    // ---- compute addressing ----
    const int wm  = (wid & 1) * 64;    // warp M offset
    const int wn  = (wid >> 1) * 32;   // warp N offset
    const int ga  = lane >> 2;         // 0..7
    const int tig = lane & 3;          // 0..3

    float acc[4][4][4];
    #pragma unroll
    for (int i = 0; i < 4; i++)
        #pragma unroll
        for (int j = 0; j < 4; j++)
            #pragma unroll
            for (int q = 0; q < 4; q++) acc[i][j][q] = 0.f;

    for (int kt = 0; kt < nkt; kt++) {
        const int s = kt % NSTG;
        cpa_wait1();
        __syncthreads();
        if (kt + 2 < nkt) ISSUE(kt + 2, (kt + 2) % NSTG);

        const float* As_ = smf + s * STAGE_FLOATS;
        const float* Bs_ = As_ + BM * PADK;

        #pragma unroll
        for (int kk = 0; kk < BK; kk += 8) {
            uint32_t af[4][4], bf[4][2];
            #pragma unroll
            for (int am = 0; am < 4; am++) {
                const int row = wm + am * 16 + ga;
                af[am][0] = __float_as_uint(As_[row * PADK + kk + tig]);
                af[am][1] = __float_as_uint(As_[(row + 8) * PADK + kk + tig]);
                af[am][2] = __float_as_uint(As_[row * PADK + kk + tig + 4]);
                af[am][3] = __float_as_uint(As_[(row + 8) * PADK + kk + tig + 4]);
            }
            #pragma unroll
            for (int an = 0; an < 4; an++) {
                const int col = wn + an * 8 + ga;
                bf[an][0] = __float_as_uint(Bs_[col * PADK + kk + tig]);
                bf[an][1] = __float_as_uint(Bs_[col * PADK + kk + tig + 4]);
            }
            #pragma unroll
            for (int am = 0; am < 4; am++)
                #pragma unroll
                for (int an = 0; an < 4; an++)
                    mma_tf32(acc[am][an], af[am], bf[an]);
        }
        __syncthreads();
    }

    // ---- epilogue ----
    #pragma unroll
    for (int am = 0; am < 4; am++) {
        const int row = bm + wm + am * 16 + ga;
        #pragma unroll
        for (int an = 0; an < 4; an++) {
            const int col = bn + wn + an * 8 + tig * 2;
            float* c0 = C + (size_t)row * ldc + col;
            float* c1 = C + (size_t)(row + 8) * ldc + col;
            *(float2*)c0 = make_float2(acc[am][an][0], acc[am][an][1]);
            *(float2*)c1 = make_float2(acc[am][an][2], acc[am][an][3]);
        }
    }
    #undef ISSUE
}

// ---------------------------------------------------------------------------
// Row softmax over HW columns; output tf32-rounded (feeds GEMM2). 1 block/row.
// ---------------------------------------------------------------------------
__global__ __launch_bounds__(256) void softmax_kernel(
    const float* __restrict__ logits, float* __restrict__ attn)
{
    const size_t row = blockIdx.x;
    const float4* src = (const float4*)(logits + row * HW);
    float4*       dst = (float4*)(attn   + row * HW);
    __shared__ float4 buf[HW / 4];
    __shared__ float  red[8];
    const int tid = threadIdx.x;

    float m = -1e30f;
    for (int i = tid; i < HW / 4; i += 256) {
        float4 v = src[i];
        buf[i] = v;
        m = fmaxf(m, fmaxf(fmaxf(v.x, v.y), fmaxf(v.z, v.w)));
    }
    #pragma unroll
    for (int o = 16; o; o >>= 1) m = fmaxf(m, __shfl_xor_sync(0xffffffffu, m, o));
    if ((tid & 31) == 0) red[tid >> 5] = m;
    __syncthreads();
    float M = red[0];
    #pragma unroll
    for (int i = 1; i < 8; i++) M = fmaxf(M, red[i]);
    __syncthreads();

    float s = 0.f;
    for (int i = tid; i < HW / 4; i += 256) {
        float4 v = buf[i];
        v.x = __expf(v.x - M); v.y = __expf(v.y - M);
        v.z = __expf(v.z - M); v.w = __expf(v.w - M);
        buf[i] = v;
        s += v.x + v.y + v.z + v.w;
    }
    #pragma unroll
    for (int o = 16; o; o >>= 1) s += __shfl_xor_sync(0xffffffffu, s, o);
    if ((tid & 31) == 0) red[tid >> 5] = s;
    __syncthreads();
    float S = 0.f;
    #pragma unroll
    for (int i = 0; i < 8; i++) S += red[i];
    const float inv = 1.0f / S;

    for (int i = tid; i < HW / 4; i += 256) {
        float4 v = buf[i];
        v.x = tf32r(v.x * inv); v.y = tf32r(v.y * inv);
        v.z = tf32r(v.z * inv); v.w = tf32r(v.w * inv);
        dst[i] = v;
    }
}

// ---------------------------------------------------------------------------
extern "C" void kernel_launch(void* const* d_in, const int* in_sizes, int n_in,
                              void* d_out, int out_size)
{
    const float* fA    = (const float*)d_in[0];
    const float* fB    = (const float*)d_in[1];
    const float* omega = (const float*)d_in[2];
    const float* scale = (const float*)d_in[3];

    float* out    = (float*)d_out;
    float* logits = out;
    float* attn   = out + (size_t)NB * HW * HW;
    float* match  = attn + (size_t)NB * HW * HW;

    float *fa_p, *fb_p, *pos_p;
    cudaGetSymbolAddress((void**)&fa_p,  g_fa);
    cudaGetSymbolAddress((void**)&fb_p,  g_fb);
    cudaGetSymbolAddress((void**)&pos_p, g_posT);

    const int smem_bytes = NSTG * STAGE_FLOATS * 4;   // 61440
    static bool attr_set = false;
    if (!attr_set) {
        cudaFuncSetAttribute(gemm_tf32_kernel,
                             cudaFuncAttributeMaxDynamicSharedMemorySize, smem_bytes);
        attr_set = true;
    }

    normalize_kernel<<<dim3(NROW, 2), 256>>>(fA, fB);
    posemb_kernel<<<512, 256>>>(omega, scale);

    // GEMM1: logits[b] = fa[b] @ fb[b]^T   (M=HW, N=HW, K=DD)
    gemm_tf32_kernel<<<dim3(HW / BN, HW / BM, NB), 256, smem_bytes>>>(
        fa_p, fb_p, logits, DD, DD, DD, HW,
        (size_t)HW * DD, (size_t)HW * DD, (size_t)HW * HW);

    softmax_kernel<<<NROW, 256>>>(logits, attn);

    // GEMM2: match[b] = attn[b] @ posT^T   (M=HW, N=DD, K=HW)
    gemm_tf32_kernel<<<dim3(DD / BN, HW / BM, NB), 256, smem_bytes>>>(
        attn, pos_p, match, HW, HW, HW, DD,
        (size_t)HW * HW, (size_t)0, (size_t)HW * DD);
}

// round 5
// speedup vs baseline: 3.2198x; 1.0616x over previous
#include <cuda_runtime.h>
#include <cstdint>

#define NB   8
#define HW   2304
#define DD   1024
#define NROW (NB * HW)

// ------------------------------ scratch ------------------------------------
__device__ float g_fa[(size_t)NROW * DD];   // normalized A (tf32-rounded, x10 = 1/TEMP)
__device__ float g_fb[(size_t)NROW * DD];   // normalized B (tf32-rounded)
__device__ float g_posT[(size_t)DD * HW];   // pos emb transposed [D][HW], tf32-rounded

// ------------------------------ helpers ------------------------------------
__device__ __forceinline__ uint32_t smem_u32(const void* p) {
    uint32_t a;
    asm("{ .reg .u64 t; cvta.to.shared.u64 t, %1; cvt.u32.u64 %0, t; }" : "=r"(a) : "l"(p));
    return a;
}
__device__ __forceinline__ float tf32r(float x) {
    uint32_t u;
    asm("cvt.rna.tf32.f32 %0, %1;" : "=r"(u) : "f"(x));
    return __uint_as_float(u);
}
__device__ __forceinline__ void cpa16(uint32_t dst, const void* src) {
    asm volatile("cp.async.cg.shared.global [%0], [%1], 16;" :: "r"(dst), "l"(src));
}
__device__ __forceinline__ void cpa_commit() {
    asm volatile("cp.async.commit_group;" ::: "memory");
}
__device__ __forceinline__ void cpa_wait1() {
    asm volatile("cp.async.wait_group 1;" ::: "memory");
}
__device__ __forceinline__ void cpa_wait0() {
    asm volatile("cp.async.wait_group 0;" ::: "memory");
}
// ldmatrix x4: four 8x8 b16 matrices == four 8x4 tf32 blocks; lane l gets
// element (row=l/4, col=l%4) (b32 units) of matrix i into reg i.
__device__ __forceinline__ void ldsm_x4(uint32_t* r, uint32_t addr) {
    asm volatile("ldmatrix.sync.aligned.m8n8.x4.shared.b16 {%0,%1,%2,%3}, [%4];"
                 : "=r"(r[0]), "=r"(r[1]), "=r"(r[2]), "=r"(r[3]) : "r"(addr));
}
// D += A * B^T via m16n8k8 tf32 (row.col)
__device__ __forceinline__ void mma_tf32(float* c, const uint32_t* a, const uint32_t* b) {
    asm volatile(
        "mma.sync.aligned.m16n8k8.row.col.f32.tf32.tf32.f32 "
        "{%0,%1,%2,%3}, {%4,%5,%6,%7}, {%8,%9}, {%0,%1,%2,%3};"
        : "+f"(c[0]), "+f"(c[1]), "+f"(c[2]), "+f"(c[3])
        : "r"(a[0]), "r"(a[1]), "r"(a[2]), "r"(a[3]), "r"(b[0]), "r"(b[1]));
}

// ---------------------------------------------------------------------------
// Row L2-normalization + tf32 rounding. grid=(NROW,2), block=256.
// ---------------------------------------------------------------------------
__global__ __launch_bounds__(256) void normalize_kernel(
    const float* __restrict__ A, const float* __restrict__ Bm)
{
    const int row   = blockIdx.x;
    const int which = blockIdx.y;
    const float* src = which ? Bm : A;
    float*       dst = which ? g_fb : g_fa;
    const size_t base = (size_t)row * DD;

    float4 v = ((const float4*)(src + base))[threadIdx.x];
    float ss = v.x * v.x + v.y * v.y + v.z * v.z + v.w * v.w;
    #pragma unroll
    for (int o = 16; o; o >>= 1) ss += __shfl_xor_sync(0xffffffffu, ss, o);

    __shared__ float ws[8];
    if ((threadIdx.x & 31) == 0) ws[threadIdx.x >> 5] = ss;
    __syncthreads();
    float tot = 0.f;
    #pragma unroll
    for (int i = 0; i < 8; i++) tot += ws[i];

    const float inv = rsqrtf(tot) * (which ? 1.0f : 10.0f);
    v.x = tf32r(v.x * inv); v.y = tf32r(v.y * inv);
    v.z = tf32r(v.z * inv); v.w = tf32r(v.w * inv);
    ((float4*)(dst + base))[threadIdx.x] = v;
}

// ---------------------------------------------------------------------------
// Fourier pos-emb written TRANSPOSED: g_posT[d][p]. grid=512 (omega rows).
// ---------------------------------------------------------------------------
__global__ __launch_bounds__(256) void posemb_kernel(
    const float* __restrict__ omega, const float* __restrict__ scale)
{
    const int k = blockIdx.x;                  // 0..511
    const float2 om = ((const float2*)omega)[k];
    const float s  = *scale;
    float* rsin = g_posT + (size_t)k * HW;
    float* rcos = g_posT + (size_t)(512 + k) * HW;

    for (int p = threadIdx.x; p < HW; p += 256) {
        const int i = p / 48, j = p % 48;
        const float gy = -1.0f + 2.0f * (float)i / 47.0f;
        const float gx = -1.0f + 2.0f * (float)j / 47.0f;
        float sn, cs;
        sincosf(s * (gx * om.x + gy * om.y), &sn, &cs);
        rsin[p] = tf32r(sn);
        rcos[p] = tf32r(cs);
    }
}

// ---------------------------------------------------------------------------
// tf32 mma.sync GEMM: C[M,N] = A[M,K] * B[N,K]^T, batched on blockIdx.z.
// Tile 128x128, BK=32, 2-stage cp.async, ldmatrix fragments, reg double-buffer.
// 8 warps, warp tile 64x32.
// ---------------------------------------------------------------------------
#define BM 128
#define BN 128
#define BK 32
#define PADK 36                         // floats; 144B row stride: 16B-aligned, conflict-free
#define STAGE_FLOATS ((BM + BN) * PADK) // 9216 floats = 36864 B
#define NSTG 2

extern __shared__ float smf[];

__global__ __launch_bounds__(256, 1)
void gemm_tf32_kernel(const float* __restrict__ A, const float* __restrict__ B,
                      float* __restrict__ C,
                      int K, int lda, int ldb, int ldc,
                      size_t sA, size_t sB, size_t sC)
{
    const uint32_t sbase = smem_u32(smf);
    const int tid  = threadIdx.x;
    const int wid  = tid >> 5;
    const int lane = tid & 31;
    const int bm = blockIdx.y * BM;
    const int bn = blockIdx.x * BN;

    A += (size_t)blockIdx.z * sA;
    B += (size_t)blockIdx.z * sB;
    C += (size_t)blockIdx.z * sC;

    // ---- loader: thread owns rows r+32i (i=0..3) at float4-col c8, A and B ----
    const int r  = tid >> 3;           // 0..31
    const int c8 = tid & 7;            // float4 index 0..7 (BK=32 -> 8 float4/row)
    const float* pa[4];
    const float* pb[4];
    uint32_t da[4], db[4];
    #pragma unroll
    for (int i = 0; i < 4; i++) {
        pa[i] = A + (size_t)(bm + r + 32 * i) * lda + c8 * 4;
        pb[i] = B + (size_t)(bn + r + 32 * i) * ldb + c8 * 4;
        da[i] = sbase + (uint32_t)((r + 32 * i) * PADK + c8 * 4) * 4;
        db[i] = da[i] + BM * PADK * 4;
    }

    const int nkt = K / BK;

    #define ISSUE(kt, s) do {                                          \
        const uint32_t o = (uint32_t)(s) * (STAGE_FLOATS * 4);         \
        const int off = (kt) * BK;                                     \
        cpa16(da[0] + o, pa[0] + off); cpa16(da[1] + o, pa[1] + off);  \
        cpa16(da[2] + o, pa[2] + off); cpa16(da[3] + o, pa[3] + off);  \
        cpa16(db[0] + o, pb[0] + off); cpa16(db[1] + o, pb[1] + off);  \
        cpa16(db[2] + o, pb[2] + off); cpa16(db[3] + o, pb[3] + off);  \
        cpa_commit();                                                  \
    } while (0)

    ISSUE(0, 0);

    // ---- compute addressing (ldmatrix lane layout) ----
    const int wm   = (wid & 1) * 64;   // warp M offset
    const int wn   = (wid >> 1) * 32;  // warp N offset
    const int lrow = lane & 7;
    const int msel = lane >> 3;        // matrix select 0..3
    // A x4 (per am): m0 rows lo/k lo, m1 rows hi/k lo, m2 rows lo/k hi, m3 rows hi/k hi
    const uint32_t aoff0 = (uint32_t)(((wm + (msel & 1) * 8 + lrow) * PADK + (msel >> 1) * 4) * 4);
    // B x4 (per j): m0 n(2j)/k lo, m1 n(2j)/k hi, m2 n(2j+1)/k lo, m3 n(2j+1)/k hi
    const uint32_t boff0 = (uint32_t)(((wn + (msel >> 1) * 8 + lrow) * PADK + (msel & 1) * 4) * 4)
                         + BM * PADK * 4;
    const int ga  = lane >> 2;
    const int tig = lane & 3;

    float acc[4][4][4];
    #pragma unroll
    for (int i = 0; i < 4; i++)
        #pragma unroll
        for (int j = 0; j < 4; j++)
            #pragma unroll
            for (int q = 0; q < 4; q++) acc[i][j][q] = 0.f;

    uint32_t af[2][4][4];   // [buf][am][4]
    uint32_t bf[2][2][4];   // [buf][j][4] : regs {b0(an=2j), b1(an=2j), b0(an=2j+1), b1(an=2j+1)}

    for (int kt = 0; kt < nkt; kt++) {
        const uint32_t stA = sbase + (uint32_t)(kt & 1) * (STAGE_FLOATS * 4);
        if (kt + 1 < nkt) { ISSUE(kt + 1, (kt + 1) & 1); cpa_wait1(); }
        else              { cpa_wait0(); }
        __syncthreads();

        // prime kk=0 into buf 0
        #pragma unroll
        for (int am = 0; am < 4; am++)
            ldsm_x4(af[0][am], stA + aoff0 + am * (16 * PADK * 4));
        #pragma unroll
        for (int j = 0; j < 2; j++)
            ldsm_x4(bf[0][j], stA + boff0 + j * (16 * PADK * 4));

        #pragma unroll
        for (int kk = 0; kk < 4; kk++) {
            const int cur = kk & 1, nxt = cur ^ 1;
            if (kk < 3) {
                const uint32_t kkb = (uint32_t)(kk + 1) * 32;  // 8 floats = 32 B
                #pragma unroll
                for (int am = 0; am < 4; am++)
                    ldsm_x4(af[nxt][am], stA + aoff0 + am * (16 * PADK * 4) + kkb);
                #pragma unroll
                for (int j = 0; j < 2; j++)
                    ldsm_x4(bf[nxt][j], stA + boff0 + j * (16 * PADK * 4) + kkb);
            }
            #pragma unroll
            for (int am = 0; am < 4; am++) {
                #pragma unroll
                for (int j = 0; j < 2; j++) {
                    mma_tf32(acc[am][2 * j],     af[cur][am], &bf[cur][j][0]);
                    mma_tf32(acc[am][2 * j + 1], af[cur][am], &bf[cur][j][2]);
                }
            }
        }
        __syncthreads();
    }

    // ---- epilogue ----
    #pragma unroll
    for (int am = 0; am < 4; am++) {
        const int row = bm + wm + am * 16 + ga;
        #pragma unroll
        for (int an = 0; an < 4; an++) {
            const int col = bn + wn + an * 8 + tig * 2;
            float* c0 = C + (size_t)row * ldc + col;
            float* c1 = C + (size_t)(row + 8) * ldc + col;
            *(float2*)c0 = make_float2(acc[am][an][0], acc[am][an][1]);
            *(float2*)c1 = make_float2(acc[am][an][2], acc[am][an][3]);
        }
    }
    #undef ISSUE
}

// ---------------------------------------------------------------------------
// Row softmax over HW columns; output tf32-rounded (feeds GEMM2). 1 block/row.
// ---------------------------------------------------------------------------
__global__ __launch_bounds__(256) void softmax_kernel(
    const float* __restrict__ logits, float* __restrict__ attn)
{
    const size_t row = blockIdx.x;
    const float4* src = (const float4*)(logits + row * HW);
    float4*       dst = (float4*)(attn   + row * HW);
    __shared__ float4 buf[HW / 4];
    __shared__ float  red[8];
    const int tid = threadIdx.x;

    float m = -1e30f;
    for (int i = tid; i < HW / 4; i += 256) {
        float4 v = src[i];
        buf[i] = v;
        m = fmaxf(m, fmaxf(fmaxf(v.x, v.y), fmaxf(v.z, v.w)));
    }
    #pragma unroll
    for (int o = 16; o; o >>= 1) m = fmaxf(m, __shfl_xor_sync(0xffffffffu, m, o));
    if ((tid & 31) == 0) red[tid >> 5] = m;
    __syncthreads();
    float M = red[0];
    #pragma unroll
    for (int i = 1; i < 8; i++) M = fmaxf(M, red[i]);
    __syncthreads();

    float s = 0.f;
    for (int i = tid; i < HW / 4; i += 256) {
        float4 v = buf[i];
        v.x = __expf(v.x - M); v.y = __expf(v.y - M);
        v.z = __expf(v.z - M); v.w = __expf(v.w - M);
        buf[i] = v;
        s += v.x + v.y + v.z + v.w;
    }
    #pragma unroll
    for (int o = 16; o; o >>= 1) s += __shfl_xor_sync(0xffffffffu, s, o);
    if ((tid & 31) == 0) red[tid >> 5] = s;
    __syncthreads();
    float S = 0.f;
    #pragma unroll
    for (int i = 0; i < 8; i++) S += red[i];
    const float inv = 1.0f / S;

    for (int i = tid; i < HW / 4; i += 256) {
        float4 v = buf[i];
        v.x = tf32r(v.x * inv); v.y = tf32r(v.y * inv);
        v.z = tf32r(v.z * inv); v.w = tf32r(v.w * inv);
        dst[i] = v;
    }
}

// ---------------------------------------------------------------------------
extern "C" void kernel_launch(void* const* d_in, const int* in_sizes, int n_in,
                              void* d_out, int out_size)
{
    const float* fA    = (const float*)d_in[0];
    const float* fB    = (const float*)d_in[1];
    const float* omega = (const float*)d_in[2];
    const float* scale = (const float*)d_in[3];

    float* out    = (float*)d_out;
    float* logits = out;
    float* attn   = out + (size_t)NB * HW * HW;
    float* match  = attn + (size_t)NB * HW * HW;

    float *fa_p, *fb_p, *pos_p;
    cudaGetSymbolAddress((void**)&fa_p,  g_fa);
    cudaGetSymbolAddress((void**)&fb_p,  g_fb);
    cudaGetSymbolAddress((void**)&pos_p, g_posT);

    const int smem_bytes = NSTG * STAGE_FLOATS * 4;   // 73728
    static bool attr_set = false;
    if (!attr_set) {
        cudaFuncSetAttribute(gemm_tf32_kernel,
                             cudaFuncAttributeMaxDynamicSharedMemorySize, smem_bytes);
        attr_set = true;
    }

    normalize_kernel<<<dim3(NROW, 2), 256>>>(fA, fB);
    posemb_kernel<<<512, 256>>>(omega, scale);

    // GEMM1: logits[b] = fa[b] @ fb[b]^T   (M=HW, N=HW, K=DD)
    gemm_tf32_kernel<<<dim3(HW / BN, HW / BM, NB), 256, smem_bytes>>>(
        fa_p, fb_p, logits, DD, DD, DD, HW,
        (size_t)HW * DD, (size_t)HW * DD, (size_t)HW * HW);

    softmax_kernel<<<NROW, 256>>>(logits, attn);

    // GEMM2: match[b] = attn[b] @ posT^T   (M=HW, N=DD, K=HW)
    gemm_tf32_kernel<<<dim3(DD / BN, HW / BM, NB), 256, smem_bytes>>>(
        attn, pos_p, match, HW, HW, HW, DD,
        (size_t)HW * HW, (size_t)0, (size_t)HW * DD);
}

// round 6
// speedup vs baseline: 4.8883x; 1.5182x over previous
#include <cuda_runtime.h>
#include <cuda_fp16.h>
#include <cstdint>

#define NB   8
#define HW   2304
#define DD   1024
#define NROW (NB * HW)

// ------------------------------ scratch ------------------------------------
__device__ __half g_fa[(size_t)NROW * DD];    // normalized A, x10 = 1/TEMP
__device__ __half g_fb[(size_t)NROW * DD];    // normalized B
__device__ __half g_posT[(size_t)DD * HW];    // pos emb transposed [D][HW]
__device__ __half g_attnh[(size_t)NROW * HW]; // fp16 copy of attn for GEMM2

// ------------------------------ helpers ------------------------------------
__device__ __forceinline__ uint32_t smem_u32(const void* p) {
    uint32_t a;
    asm("{ .reg .u64 t; cvta.to.shared.u64 t, %1; cvt.u32.u64 %0, t; }" : "=r"(a) : "l"(p));
    return a;
}
__device__ __forceinline__ void cpa16(uint32_t dst, const void* src) {
    asm volatile("cp.async.cg.shared.global [%0], [%1], 16;" :: "r"(dst), "l"(src));
}
__device__ __forceinline__ void cpa_commit() {
    asm volatile("cp.async.commit_group;" ::: "memory");
}
__device__ __forceinline__ void cpa_wait1() {
    asm volatile("cp.async.wait_group 1;" ::: "memory");
}
__device__ __forceinline__ void cpa_wait0() {
    asm volatile("cp.async.wait_group 0;" ::: "memory");
}
__device__ __forceinline__ void ldsm_x4(uint32_t* r, uint32_t addr) {
    asm volatile("ldmatrix.sync.aligned.m8n8.x4.shared.b16 {%0,%1,%2,%3}, [%4];"
                 : "=r"(r[0]), "=r"(r[1]), "=r"(r[2]), "=r"(r[3]) : "r"(addr));
}
// D += A * B^T via m16n8k16 fp16 inputs, fp32 accum (row.col)
__device__ __forceinline__ void mma_f16(float* c, const uint32_t* a, const uint32_t* b) {
    asm volatile(
        "mma.sync.aligned.m16n8k16.row.col.f32.f16.f16.f32 "
        "{%0,%1,%2,%3}, {%4,%5,%6,%7}, {%8,%9}, {%0,%1,%2,%3};"
        : "+f"(c[0]), "+f"(c[1]), "+f"(c[2]), "+f"(c[3])
        : "r"(a[0]), "r"(a[1]), "r"(a[2]), "r"(a[3]), "r"(b[0]), "r"(b[1]));
}

// ---------------------------------------------------------------------------
// Row L2-normalization -> fp16 scratch. grid=(NROW,2), block=256.
// ---------------------------------------------------------------------------
__global__ __launch_bounds__(256) void normalize_kernel(
    const float* __restrict__ A, const float* __restrict__ Bm)
{
    const int row   = blockIdx.x;
    const int which = blockIdx.y;
    const float* src = which ? Bm : A;
    __half*      dst = which ? g_fb : g_fa;
    const size_t base = (size_t)row * DD;

    float4 v = ((const float4*)(src + base))[threadIdx.x];
    float ss = v.x * v.x + v.y * v.y + v.z * v.z + v.w * v.w;
    #pragma unroll
    for (int o = 16; o; o >>= 1) ss += __shfl_xor_sync(0xffffffffu, ss, o);

    __shared__ float ws[8];
    if ((threadIdx.x & 31) == 0) ws[threadIdx.x >> 5] = ss;
    __syncthreads();
    float tot = 0.f;
    #pragma unroll
    for (int i = 0; i < 8; i++) tot += ws[i];

    const float inv = rsqrtf(tot) * (which ? 1.0f : 10.0f);
    __half2 h0 = __floats2half2_rn(v.x * inv, v.y * inv);
    __half2 h1 = __floats2half2_rn(v.z * inv, v.w * inv);
    uint2 pack = make_uint2(*(uint32_t*)&h0, *(uint32_t*)&h1);
    ((uint2*)(dst + base))[threadIdx.x] = pack;
}

// ---------------------------------------------------------------------------
// Fourier pos-emb TRANSPOSED: g_posT[d][p], fp16. grid=512 (omega rows).
// ---------------------------------------------------------------------------
__global__ __launch_bounds__(256) void posemb_kernel(
    const float* __restrict__ omega, const float* __restrict__ scale)
{
    const int k = blockIdx.x;                  // 0..511
    const float2 om = ((const float2*)omega)[k];
    const float s  = *scale;
    __half* rsin = g_posT + (size_t)k * HW;
    __half* rcos = g_posT + (size_t)(512 + k) * HW;

    for (int p = threadIdx.x; p < HW; p += 256) {
        const int i = p / 48, j = p % 48;
        const float gy = -1.0f + 2.0f * (float)i / 47.0f;
        const float gx = -1.0f + 2.0f * (float)j / 47.0f;
        float sn, cs;
        sincosf(s * (gx * om.x + gy * om.y), &sn, &cs);
        rsin[p] = __float2half_rn(sn);
        rcos[p] = __float2half_rn(cs);
    }
}

// ---------------------------------------------------------------------------
// fp16 mma.sync GEMM: C[M,N](f32) = A[M,K] * B[N,K]^T, batched on blockIdx.z.
// Tile 128x128, BK=32 (halves), 3-stage cp.async, ldmatrix, reg double-buffer.
// 8 warps, warp tile 64x32.
// ---------------------------------------------------------------------------
#define BM 128
#define BN 128
#define BK 32
#define PADK 40                          // halves; 80B row stride, conflict-free
#define STAGE_BYTES ((BM + BN) * PADK * 2)   // 20480 B
#define NSTG 3

extern __shared__ __half smh[];

__global__ __launch_bounds__(256, 1)
void gemm_f16_kernel(const __half* __restrict__ A, const __half* __restrict__ B,
                     float* __restrict__ C,
                     int K, int lda, int ldb, int ldc,
                     size_t sA, size_t sB, size_t sC)
{
    const uint32_t sbase = smem_u32(smh);
    const int tid  = threadIdx.x;
    const int wid  = tid >> 5;
    const int lane = tid & 31;
    const int bm = blockIdx.y * BM;
    const int bn = blockIdx.x * BN;

    A += (size_t)blockIdx.z * sA;
    B += (size_t)blockIdx.z * sB;
    C += (size_t)blockIdx.z * sC;

    // ---- loader: thread owns rows r, r+64 at 16B-col c4, for A and B ----
    const int r  = tid >> 2;           // 0..63
    const int c4 = tid & 3;            // 0..3 (16B units; BK=32 halves = 64B/row)
    const __half* pa0 = A + (size_t)(bm + r) * lda + c4 * 8;
    const __half* pa1 = pa0 + (size_t)64 * lda;
    const __half* pb0 = B + (size_t)(bn + r) * ldb + c4 * 8;
    const __half* pb1 = pb0 + (size_t)64 * ldb;
    const uint32_t da0 = sbase + (uint32_t)(r * PADK + c4 * 8) * 2;
    const uint32_t da1 = da0 + 64 * PADK * 2;
    const uint32_t db0 = da0 + BM * PADK * 2;
    const uint32_t db1 = db0 + 64 * PADK * 2;

    const int nkt = K / BK;

    #define ISSUE(kt, s) do {                                   \
        const uint32_t o = (uint32_t)(s) * STAGE_BYTES;         \
        const int off = (kt) * BK;                              \
        cpa16(da0 + o, pa0 + off); cpa16(da1 + o, pa1 + off);   \
        cpa16(db0 + o, pb0 + off); cpa16(db1 + o, pb1 + off);   \
        cpa_commit();                                           \
    } while (0)

    ISSUE(0, 0);
    ISSUE(1, 1);

    // ---- compute addressing (ldmatrix lane layout) ----
    const int wm   = (wid & 1) * 64;   // warp M offset
    const int wn   = (wid >> 1) * 32;  // warp N offset
    const int lrow = lane & 7;
    const int msel = lane >> 3;        // matrix select 0..3
    // A x4: m0 rows0-7/k0-7, m1 rows8-15/k0-7, m2 rows0-7/k8-15, m3 rows8-15/k8-15
    const uint32_t aoff0 = (uint32_t)(((wm + (msel & 1) * 8 + lrow) * PADK + (msel >> 1) * 8) * 2);
    // B x4: m0 n0-7/k0-7, m1 n0-7/k8-15, m2 n8-15/k0-7, m3 n8-15/k8-15
    const uint32_t boff0 = (uint32_t)(((wn + (msel >> 1) * 8 + lrow) * PADK + (msel & 1) * 8) * 2)
                         + BM * PADK * 2;
    const int ga  = lane >> 2;
    const int tig = lane & 3;

    float acc[4][4][4];
    #pragma unroll
    for (int i = 0; i < 4; i++)
        #pragma unroll
        for (int j = 0; j < 4; j++)
            #pragma unroll
            for (int q = 0; q < 4; q++) acc[i][j][q] = 0.f;

    uint32_t af[2][4][4];   // [buf][am][4]
    uint32_t bf[2][2][4];   // [buf][jb][4]: {b0(n=2jb),b1(n=2jb),b0(n=2jb+1),b1(n=2jb+1)}

    for (int kt = 0; kt < nkt; kt++) {
        const uint32_t stA = sbase + (uint32_t)(kt % NSTG) * STAGE_BYTES;
        if (kt + 1 < nkt) cpa_wait1(); else cpa_wait0();
        __syncthreads();
        if (kt + 2 < nkt) ISSUE(kt + 2, (kt + 2) % NSTG);

        // prime kk=0 into buf 0
        #pragma unroll
        for (int am = 0; am < 4; am++)
            ldsm_x4(af[0][am], stA + aoff0 + am * (16 * PADK * 2));
        #pragma unroll
        for (int jb = 0; jb < 2; jb++)
            ldsm_x4(bf[0][jb], stA + boff0 + jb * (16 * PADK * 2));

        #pragma unroll
        for (int kk = 0; kk < 2; kk++) {       // BK=32 -> 2 x k16
            const int cur = kk & 1, nxt = cur ^ 1;
            if (kk < 1) {
                const uint32_t kkb = 32;       // 16 halves = 32 B
                #pragma unroll
                for (int am = 0; am < 4; am++)
                    ldsm_x4(af[nxt][am], stA + aoff0 + am * (16 * PADK * 2) + kkb);
                #pragma unroll
                for (int jb = 0; jb < 2; jb++)
                    ldsm_x4(bf[nxt][jb], stA + boff0 + jb * (16 * PADK * 2) + kkb);
            }
            #pragma unroll
            for (int am = 0; am < 4; am++) {
                #pragma unroll
                for (int jb = 0; jb < 2; jb++) {
                    mma_f16(acc[am][2 * jb],     af[cur][am], &bf[cur][jb][0]);
                    mma_f16(acc[am][2 * jb + 1], af[cur][am], &bf[cur][jb][2]);
                }
            }
        }
    }

    // ---- epilogue ----
    #pragma unroll
    for (int am = 0; am < 4; am++) {
        const int row = bm + wm + am * 16 + ga;
        #pragma unroll
        for (int an = 0; an < 4; an++) {
            const int col = bn + wn + an * 8 + tig * 2;
            float* c0 = C + (size_t)row * ldc + col;
            float* c1 = C + (size_t)(row + 8) * ldc + col;
            *(float2*)c0 = make_float2(acc[am][an][0], acc[am][an][1]);
            *(float2*)c1 = make_float2(acc[am][an][2], acc[am][an][3]);
        }
    }
    #undef ISSUE
}

// ---------------------------------------------------------------------------
// Row softmax over HW columns; writes fp32 attn (output) + fp16 copy (GEMM2).
// ---------------------------------------------------------------------------
__global__ __launch_bounds__(256) void softmax_kernel(
    const float* __restrict__ logits, float* __restrict__ attn)
{
    const size_t row = blockIdx.x;
    const float4* src = (const float4*)(logits + row * HW);
    float4*       dst = (float4*)(attn   + row * HW);
    uint2*        dsth = (uint2*)(g_attnh + row * HW);
    __shared__ float4 buf[HW / 4];
    __shared__ float  red[8];
    const int tid = threadIdx.x;

    float m = -1e30f;
    for (int i = tid; i < HW / 4; i += 256) {
        float4 v = src[i];
        buf[i] = v;
        m = fmaxf(m, fmaxf(fmaxf(v.x, v.y), fmaxf(v.z, v.w)));
    }
    #pragma unroll
    for (int o = 16; o; o >>= 1) m = fmaxf(m, __shfl_xor_sync(0xffffffffu, m, o));
    if ((tid & 31) == 0) red[tid >> 5] = m;
    __syncthreads();
    float M = red[0];
    #pragma unroll
    for (int i = 1; i < 8; i++) M = fmaxf(M, red[i]);
    __syncthreads();

    float s = 0.f;
    for (int i = tid; i < HW / 4; i += 256) {
        float4 v = buf[i];
        v.x = __expf(v.x - M); v.y = __expf(v.y - M);
        v.z = __expf(v.z - M); v.w = __expf(v.w - M);
        buf[i] = v;
        s += v.x + v.y + v.z + v.w;
    }
    #pragma unroll
    for (int o = 16; o; o >>= 1) s += __shfl_xor_sync(0xffffffffu, s, o);
    if ((tid & 31) == 0) red[tid >> 5] = s;
    __syncthreads();
    float S = 0.f;
    #pragma unroll
    for (int i = 0; i < 8; i++) S += red[i];
    const float inv = 1.0f / S;

    for (int i = tid; i < HW / 4; i += 256) {
        float4 v = buf[i];
        v.x *= inv; v.y *= inv; v.z *= inv; v.w *= inv;
        dst[i] = v;
        __half2 h0 = __floats2half2_rn(v.x, v.y);
        __half2 h1 = __floats2half2_rn(v.z, v.w);
        dsth[i] = make_uint2(*(uint32_t*)&h0, *(uint32_t*)&h1);
    }
}

// ---------------------------------------------------------------------------
extern "C" void kernel_launch(void* const* d_in, const int* in_sizes, int n_in,
                              void* d_out, int out_size)
{
    const float* fA    = (const float*)d_in[0];
    const float* fB    = (const float*)d_in[1];
    const float* omega = (const float*)d_in[2];
    const float* scale = (const float*)d_in[3];

    float* out    = (float*)d_out;
    float* logits = out;
    float* attn   = out + (size_t)NB * HW * HW;
    float* match  = attn + (size_t)NB * HW * HW;

    __half *fa_p, *fb_p, *pos_p, *at_p;
    cudaGetSymbolAddress((void**)&fa_p,  g_fa);
    cudaGetSymbolAddress((void**)&fb_p,  g_fb);
    cudaGetSymbolAddress((void**)&pos_p, g_posT);
    cudaGetSymbolAddress((void**)&at_p,  g_attnh);

    const int smem_bytes = NSTG * STAGE_BYTES;   // 61440
    static bool attr_set = false;
    if (!attr_set) {
        cudaFuncSetAttribute(gemm_f16_kernel,
                             cudaFuncAttributeMaxDynamicSharedMemorySize, smem_bytes);
        attr_set = true;
    }

    normalize_kernel<<<dim3(NROW, 2), 256>>>(fA, fB);
    posemb_kernel<<<512, 256>>>(omega, scale);

    // GEMM1: logits[b] = fa[b] @ fb[b]^T   (M=HW, N=HW, K=DD)
    gemm_f16_kernel<<<dim3(HW / BN, HW / BM, NB), 256, smem_bytes>>>(
        fa_p, fb_p, logits, DD, DD, DD, HW,
        (size_t)HW * DD, (size_t)HW * DD, (size_t)HW * HW);

    softmax_kernel<<<NROW, 256>>>(logits, attn);

    // GEMM2: match[b] = attn_h[b] @ posT^T   (M=HW, N=DD, K=HW)
    gemm_f16_kernel<<<dim3(DD / BN, HW / BM, NB), 256, smem_bytes>>>(
        at_p, pos_p, match, HW, HW, HW, DD,
        (size_t)HW * HW, (size_t)0, (size_t)HW * DD);
}

// round 7
// speedup vs baseline: 5.2255x; 1.0690x over previous
#include <cuda_runtime.h>
#include <cuda_fp16.h>
#include <cstdint>

#define NB   8
#define HW   2304
#define DD   1024
#define NROW (NB * HW)

// ------------------------------ scratch ------------------------------------
__device__ __half g_fa[(size_t)NROW * DD];    // normalized A, x10 = 1/TEMP
__device__ __half g_fb[(size_t)NROW * DD];    // normalized B
__device__ __half g_posT[(size_t)DD * HW];    // pos emb transposed [D][HW]
__device__ __half g_attnh[(size_t)NROW * HW]; // fp16 copy of attn for GEMM2

// ------------------------------ helpers ------------------------------------
__device__ __forceinline__ uint32_t smem_u32(const void* p) {
    uint32_t a;
    asm("{ .reg .u64 t; cvta.to.shared.u64 t, %1; cvt.u32.u64 %0, t; }" : "=r"(a) : "l"(p));
    return a;
}
__device__ __forceinline__ void cpa16(uint32_t dst, const void* src) {
    asm volatile("cp.async.cg.shared.global [%0], [%1], 16;" :: "r"(dst), "l"(src));
}
__device__ __forceinline__ void cpa_commit() {
    asm volatile("cp.async.commit_group;" ::: "memory");
}
__device__ __forceinline__ void cpa_wait1() {
    asm volatile("cp.async.wait_group 1;" ::: "memory");
}
__device__ __forceinline__ void cpa_wait0() {
    asm volatile("cp.async.wait_group 0;" ::: "memory");
}
__device__ __forceinline__ void ldsm_x4(uint32_t* r, uint32_t addr) {
    asm volatile("ldmatrix.sync.aligned.m8n8.x4.shared.b16 {%0,%1,%2,%3}, [%4];"
                 : "=r"(r[0]), "=r"(r[1]), "=r"(r[2]), "=r"(r[3]) : "r"(addr));
}
// D += A * B^T via m16n8k16 fp16 inputs, fp32 accum (row.col)
__device__ __forceinline__ void mma_f16(float* c, const uint32_t* a, const uint32_t* b) {
    asm volatile(
        "mma.sync.aligned.m16n8k16.row.col.f32.f16.f16.f32 "
        "{%0,%1,%2,%3}, {%4,%5,%6,%7}, {%8,%9}, {%0,%1,%2,%3};"
        : "+f"(c[0]), "+f"(c[1]), "+f"(c[2]), "+f"(c[3])
        : "r"(a[0]), "r"(a[1]), "r"(a[2]), "r"(a[3]), "r"(b[0]), "r"(b[1]));
}

// ---------------------------------------------------------------------------
// Row L2-normalization -> fp16 scratch. grid=(NROW,2), block=256.
// ---------------------------------------------------------------------------
__global__ __launch_bounds__(256) void normalize_kernel(
    const float* __restrict__ A, const float* __restrict__ Bm)
{
    const int row   = blockIdx.x;
    const int which = blockIdx.y;
    const float* src = which ? Bm : A;
    __half*      dst = which ? g_fb : g_fa;
    const size_t base = (size_t)row * DD;

    float4 v = ((const float4*)(src + base))[threadIdx.x];
    float ss = v.x * v.x + v.y * v.y + v.z * v.z + v.w * v.w;
    #pragma unroll
    for (int o = 16; o; o >>= 1) ss += __shfl_xor_sync(0xffffffffu, ss, o);

    __shared__ float ws[8];
    if ((threadIdx.x & 31) == 0) ws[threadIdx.x >> 5] = ss;
    __syncthreads();
    float tot = 0.f;
    #pragma unroll
    for (int i = 0; i < 8; i++) tot += ws[i];

    const float inv = rsqrtf(tot) * (which ? 1.0f : 10.0f);
    __half2 h0 = __floats2half2_rn(v.x * inv, v.y * inv);
    __half2 h1 = __floats2half2_rn(v.z * inv, v.w * inv);
    uint2 pack = make_uint2(*(uint32_t*)&h0, *(uint32_t*)&h1);
    ((uint2*)(dst + base))[threadIdx.x] = pack;
}

// ---------------------------------------------------------------------------
// Fourier pos-emb TRANSPOSED: g_posT[d][p], fp16. grid=512 (omega rows).
// ---------------------------------------------------------------------------
__global__ __launch_bounds__(256) void posemb_kernel(
    const float* __restrict__ omega, const float* __restrict__ scale)
{
    const int k = blockIdx.x;                  // 0..511
    const float2 om = ((const float2*)omega)[k];
    const float s  = *scale;
    __half* rsin = g_posT + (size_t)k * HW;
    __half* rcos = g_posT + (size_t)(512 + k) * HW;

    for (int p = threadIdx.x; p < HW; p += 256) {
        const int i = p / 48, j = p % 48;
        const float gy = -1.0f + 2.0f * (float)i / 47.0f;
        const float gx = -1.0f + 2.0f * (float)j / 47.0f;
        float sn, cs;
        sincosf(s * (gx * om.x + gy * om.y), &sn, &cs);
        rsin[p] = __float2half_rn(sn);
        rcos[p] = __float2half_rn(cs);
    }
}

// ---------------------------------------------------------------------------
// fp16 mma.sync GEMM: C[M,N](f32) = A[M,K] * B[N,K]^T, batched on blockIdx.z.
// Block tile 128x256, warp tile 64x64 (8 warps, 2x4), BK=32 halves,
// 3-stage cp.async, ldmatrix fragments with register double-buffering.
// ---------------------------------------------------------------------------
#define BM 128
#define BN 256
#define BK 32
#define PADK 40                          // halves; 80B row stride, conflict-free
#define STAGE_BYTES ((BM + BN) * PADK * 2)   // 30720 B
#define NSTG 3

extern __shared__ __half smh[];

__global__ __launch_bounds__(256, 1)
void gemm_f16_kernel(const __half* __restrict__ A, const __half* __restrict__ B,
                     float* __restrict__ C,
                     int K, int lda, int ldb, int ldc,
                     size_t sA, size_t sB, size_t sC)
{
    const uint32_t sbase = smem_u32(smh);
    const int tid  = threadIdx.x;
    const int wid  = tid >> 5;
    const int lane = tid & 31;
    const int bm = blockIdx.y * BM;
    const int bn = blockIdx.x * BN;

    A += (size_t)blockIdx.z * sA;
    B += (size_t)blockIdx.z * sB;
    C += (size_t)blockIdx.z * sC;

    // ---- loader: thread owns row lr (A: 1 row, B: 2 rows), 32B (2x16B) ----
    const int lr = tid >> 1;           // 0..127
    const int lc = (tid & 1) * 16;     // halves offset: 0 or 16
    const __half* pa  = A + (size_t)(bm + lr) * lda + lc;
    const __half* pb0 = B + (size_t)(bn + lr) * ldb + lc;
    const __half* pb1 = pb0 + (size_t)128 * ldb;
    const uint32_t daa = sbase + (uint32_t)(lr * PADK + lc) * 2;
    const uint32_t db0 = sbase + BM * PADK * 2 + (uint32_t)(lr * PADK + lc) * 2;
    const uint32_t db1 = db0 + 128 * PADK * 2;

    const int nkt = K / BK;

    #define ISSUE(kt, s) do {                                     \
        const uint32_t o = (uint32_t)(s) * STAGE_BYTES;           \
        const int off = (kt) * BK;                                \
        cpa16(daa + o,      pa  + off);                           \
        cpa16(daa + o + 16, pa  + off + 8);                       \
        cpa16(db0 + o,      pb0 + off);                           \
        cpa16(db0 + o + 16, pb0 + off + 8);                       \
        cpa16(db1 + o,      pb1 + off);                           \
        cpa16(db1 + o + 16, pb1 + off + 8);                       \
        cpa_commit();                                             \
    } while (0)

    ISSUE(0, 0);
    ISSUE(1, 1);

    // ---- compute addressing (ldmatrix lane layout) ----
    const int wm   = (wid & 1) * 64;   // warp M offset (2 rows of warps)
    const int wn   = (wid >> 1) * 64;  // warp N offset (4 cols of warps)
    const int lrow = lane & 7;
    const int msel = lane >> 3;        // matrix select 0..3
    // A x4: m0 rows0-7/k0-7, m1 rows8-15/k0-7, m2 rows0-7/k8-15, m3 rows8-15/k8-15
    const uint32_t aoff0 = (uint32_t)(((wm + (msel & 1) * 8 + lrow) * PADK + (msel >> 1) * 8) * 2);
    // B x4: m0 n0-7/k0-7, m1 n0-7/k8-15, m2 n8-15/k0-7, m3 n8-15/k8-15
    const uint32_t boff0 = (uint32_t)(((wn + (msel >> 1) * 8 + lrow) * PADK + (msel & 1) * 8) * 2)
                         + BM * PADK * 2;
    const int ga  = lane >> 2;
    const int tig = lane & 3;

    float acc[4][8][4];
    #pragma unroll
    for (int i = 0; i < 4; i++)
        #pragma unroll
        for (int j = 0; j < 8; j++)
            #pragma unroll
            for (int q = 0; q < 4; q++) acc[i][j][q] = 0.f;

    uint32_t af[2][4][4];   // [buf][am][4]
    uint32_t bf[2][4][4];   // [buf][jb][4]: {b0(n=2jb),b1(n=2jb),b0(n=2jb+1),b1(n=2jb+1)}

    for (int kt = 0; kt < nkt; kt++) {
        const uint32_t stA = sbase + (uint32_t)(kt % NSTG) * STAGE_BYTES;
        if (kt + 1 < nkt) cpa_wait1(); else cpa_wait0();
        __syncthreads();
        if (kt + 2 < nkt) ISSUE(kt + 2, (kt + 2) % NSTG);

        // prime kk=0 into buf 0
        #pragma unroll
        for (int am = 0; am < 4; am++)
            ldsm_x4(af[0][am], stA + aoff0 + am * (16 * PADK * 2));
        #pragma unroll
        for (int jb = 0; jb < 4; jb++)
            ldsm_x4(bf[0][jb], stA + boff0 + jb * (16 * PADK * 2));

        #pragma unroll
        for (int kk = 0; kk < 2; kk++) {       // BK=32 -> 2 x k16
            const int cur = kk & 1, nxt = cur ^ 1;
            if (kk < 1) {
                const uint32_t kkb = 32;       // 16 halves = 32 B
                #pragma unroll
                for (int am = 0; am < 4; am++)
                    ldsm_x4(af[nxt][am], stA + aoff0 + am * (16 * PADK * 2) + kkb);
                #pragma unroll
                for (int jb = 0; jb < 4; jb++)
                    ldsm_x4(bf[nxt][jb], stA + boff0 + jb * (16 * PADK * 2) + kkb);
            }
            #pragma unroll
            for (int am = 0; am < 4; am++) {
                #pragma unroll
                for (int jb = 0; jb < 4; jb++) {
                    mma_f16(acc[am][2 * jb],     af[cur][am], &bf[cur][jb][0]);
                    mma_f16(acc[am][2 * jb + 1], af[cur][am], &bf[cur][jb][2]);
                }
            }
        }
    }

    // ---- epilogue ----
    #pragma unroll
    for (int am = 0; am < 4; am++) {
        const int row = bm + wm + am * 16 + ga;
        #pragma unroll
        for (int an = 0; an < 8; an++) {
            const int col = bn + wn + an * 8 + tig * 2;
            float* c0 = C + (size_t)row * ldc + col;
            float* c1 = C + (size_t)(row + 8) * ldc + col;
            *(float2*)c0 = make_float2(acc[am][an][0], acc[am][an][1]);
            *(float2*)c1 = make_float2(acc[am][an][2], acc[am][an][3]);
        }
    }
    #undef ISSUE
}

// ---------------------------------------------------------------------------
// Row softmax over HW columns; writes fp32 attn (output) + fp16 copy (GEMM2).
// ---------------------------------------------------------------------------
__global__ __launch_bounds__(256) void softmax_kernel(
    const float* __restrict__ logits, float* __restrict__ attn)
{
    const size_t row = blockIdx.x;
    const float4* src = (const float4*)(logits + row * HW);
    float4*       dst = (float4*)(attn   + row * HW);
    uint2*        dsth = (uint2*)(g_attnh + row * HW);
    __shared__ float4 buf[HW / 4];
    __shared__ float  red[8];
    const int tid = threadIdx.x;

    float m = -1e30f;
    for (int i = tid; i < HW / 4; i += 256) {
        float4 v = src[i];
        buf[i] = v;
        m = fmaxf(m, fmaxf(fmaxf(v.x, v.y), fmaxf(v.z, v.w)));
    }
    #pragma unroll
    for (int o = 16; o; o >>= 1) m = fmaxf(m, __shfl_xor_sync(0xffffffffu, m, o));
    if ((tid & 31) == 0) red[tid >> 5] = m;
    __syncthreads();
    float M = red[0];
    #pragma unroll
    for (int i = 1; i < 8; i++) M = fmaxf(M, red[i]);
    __syncthreads();

    float s = 0.f;
    for (int i = tid; i < HW / 4; i += 256) {
        float4 v = buf[i];
        v.x = __expf(v.x - M); v.y = __expf(v.y - M);
        v.z = __expf(v.z - M); v.w = __expf(v.w - M);
        buf[i] = v;
        s += v.x + v.y + v.z + v.w;
    }
    #pragma unroll
    for (int o = 16; o; o >>= 1) s += __shfl_xor_sync(0xffffffffu, s, o);
    if ((tid & 31) == 0) red[tid >> 5] = s;
    __syncthreads();
    float S = 0.f;
    #pragma unroll
    for (int i = 0; i < 8; i++) S += red[i];
    const float inv = 1.0f / S;

    for (int i = tid; i < HW / 4; i += 256) {
        float4 v = buf[i];
        v.x *= inv; v.y *= inv; v.z *= inv; v.w *= inv;
        dst[i] = v;
        __half2 h0 = __floats2half2_rn(v.x, v.y);
        __half2 h1 = __floats2half2_rn(v.z, v.w);
        dsth[i] = make_uint2(*(uint32_t*)&h0, *(uint32_t*)&h1);
    }
}

// ---------------------------------------------------------------------------
extern "C" void kernel_launch(void* const* d_in, const int* in_sizes, int n_in,
                              void* d_out, int out_size)
{
    const float* fA    = (const float*)d_in[0];
    const float* fB    = (const float*)d_in[1];
    const float* omega = (const float*)d_in[2];
    const float* scale = (const float*)d_in[3];

    float* out    = (float*)d_out;
    float* logits = out;
    float* attn   = out + (size_t)NB * HW * HW;
    float* match  = attn + (size_t)NB * HW * HW;

    __half *fa_p, *fb_p, *pos_p, *at_p;
    cudaGetSymbolAddress((void**)&fa_p,  g_fa);
    cudaGetSymbolAddress((void**)&fb_p,  g_fb);
    cudaGetSymbolAddress((void**)&pos_p, g_posT);
    cudaGetSymbolAddress((void**)&at_p,  g_attnh);

    const int smem_bytes = NSTG * STAGE_BYTES;   // 92160
    static bool attr_set = false;
    if (!attr_set) {
        cudaFuncSetAttribute(gemm_f16_kernel,
                             cudaFuncAttributeMaxDynamicSharedMemorySize, smem_bytes);
        attr_set = true;
    }

    normalize_kernel<<<dim3(NROW, 2), 256>>>(fA, fB);
    posemb_kernel<<<512, 256>>>(omega, scale);

    // GEMM1: logits[b] = fa[b] @ fb[b]^T   (M=HW, N=HW, K=DD)
    gemm_f16_kernel<<<dim3(HW / BN, HW / BM, NB), 256, smem_bytes>>>(
        fa_p, fb_p, logits, DD, DD, DD, HW,
        (size_t)HW * DD, (size_t)HW * DD, (size_t)HW * HW);

    softmax_kernel<<<NROW, 256>>>(logits, attn);

    // GEMM2: match[b] = attn_h[b] @ posT^T   (M=HW, N=DD, K=HW)
    gemm_f16_kernel<<<dim3(DD / BN, HW / BM, NB), 256, smem_bytes>>>(
        at_p, pos_p, match, HW, HW, HW, DD,
        (size_t)HW * HW, (size_t)0, (size_t)HW * DD);
}